// round 16
// baseline (speedup 1.0000x reference)
#include <cuda_runtime.h>
#include <cstdint>
#include <math.h>

// ---------------------------------------------------------------------------
// HiddenWFACRF: B=32, T=1024, L=128, S=64
//
// LITERAL f32 replication of the jax reference, targeting XLA:GPU bit
// behavior (jax-cuda on the GB300 itself):
//   * exp/log = libdevice (__nv_expf/__nv_logf) == CUDA expf()/logf()
//   * LSE sums follow XLA:GPU reduction schedules:
//       - column reductions (k-sum, l-sum, bstep-sum over middle axis):
//         32 partials, partial[t] = sum over rows {t, t+32, t+64, ...}
//         ascending, then binary tree combine (16,8,4,2,1)
//       - row reduction (decode LSE over minor S=64):
//         partial[t] = x[t] + x[t+32], then same tree
//     (emulated sequentially per thread; bit-identical to the shfl tree)
//   * maxes are order-free (any schedule gives identical bits)
//
//  forward (carry last[64] f32, unnormalized):
//    lsi[l,s] = fl( fl(xl[l]+xs[s]) + fl( logf(TREE_k expf(fl(last[k]+tr[k,l,s]) - amax)) + amax ) )
//    last'[s] = fl( logf(TREE_l expf(fl(lsi[l,s] - amax2))) + amax2 )
//  backward:
//    w[l,s] = fl(lsl[i][l,s] + ft[s]);  score[l] = TREE-LSE_s(w)
//    m = first-index argmax (jnp.argmax)
//    ft'[s'] = TREE-LSE over row m's 64 terms (masked rows = exact 0.0f terms)
// Output: float32 labels, [B,T] row-major.
// ---------------------------------------------------------------------------

#define L_DIM 128
#define S_DIM 64
#define T_DIM 1024
#define B_DIM 32

__device__ __align__(16) float g_LSL[(size_t)B_DIM * T_DIM * 8192];  // 1 GiB
__device__ unsigned g_cnt[B_DIM];

// in-place halving tree over 32 partials == lane-0 result of the
// shfl.down(16,8,4,2,1) warp tree
__device__ __forceinline__ float tree32(float* A) {
    #pragma unroll
    for (int h = 16; h >= 1; h >>= 1)
        #pragma unroll 1
        for (int t = 0; t < h; ++t) A[t] = A[t] + A[t + h];
    return A[0];
}

// ----------------------------------------------------------------- zero ----
__global__ void zero_cnt_kernel() {
    if (threadIdx.x < B_DIM) g_cnt[threadIdx.x] = 0u;
}

// ------------------------------------------------------------- forward -----
// 128 CTAs: 4 per batch (quarters of the 8192 (l,s) pairs), 1024 threads.
__global__ __launch_bounds__(1024) void fwd_literal(const float* __restrict__ xl,
                                                    const float* __restrict__ xs,
                                                    const float* __restrict__ tr) {
    __shared__ float s_last[S_DIM];
    __shared__ float s_lsi[8192];
    __shared__ float s_xl[L_DIM];
    __shared__ float s_xs[S_DIM];

    const int cta = blockIdx.x;
    const int b = cta >> 2, q = cta & 3;
    const int tid = threadIdx.x;
    const size_t rbase = (size_t)b * T_DIM;

    // ---- row 0: lsi = base = fl(xl + xs)
    if (tid < L_DIM) s_xl[tid] = xl[rbase * L_DIM + tid];
    if (tid < S_DIM) s_xs[tid] = xs[rbase * S_DIM + tid];
    __syncthreads();
    for (int p = tid; p < 8192; p += 1024) {
        float v = s_xl[p >> 6] + s_xs[p & 63];
        s_lsi[p] = v;
        if (q == 0) g_LSL[rbase * 8192 + p] = v;
    }
    __syncthreads();
    if (tid < S_DIM) {            // last0 = LSE over l: strided-32 partials + tree
        float amax = -INFINITY;
        for (int l = 0; l < L_DIM; ++l) amax = fmaxf(amax, s_lsi[l * 64 + tid]);
        float A[32];
        #pragma unroll 1
        for (int t = 0; t < 32; ++t) {
            float a = expf(s_lsi[t * 64 + tid] - amax);
            a = a + expf(s_lsi[(t + 32) * 64 + tid] - amax);
            a = a + expf(s_lsi[(t + 64) * 64 + tid] - amax);
            a = a + expf(s_lsi[(t + 96) * 64 + tid] - amax);
            A[t] = a;
        }
        s_last[tid] = logf(tree32(A)) + amax;
    }
    __syncthreads();

    // ---- steps 1..T-1
    for (int i = 1; i < T_DIM; ++i) {
        if (tid < L_DIM) s_xl[tid] = xl[(rbase + i) * L_DIM + tid];
        if (tid < S_DIM) s_xs[tid] = xs[(rbase + i) * S_DIM + tid];
        __syncthreads();

        #pragma unroll 1
        for (int t2 = 0; t2 < 2; ++t2) {
            const int p = q * 2048 + t2 * 1024 + tid;   // (l,s): l = p>>6, s = p&63
            const float* tp = tr + p;                   // tr[k*8192 + p]
            float amax = -INFINITY;
            for (int k = 0; k < S_DIM; ++k)
                amax = fmaxf(amax, s_last[k] + tp[k * 8192]);
            float A[32];
            #pragma unroll 1
            for (int t = 0; t < 32; ++t) {              // partial: k = t, then t+32
                float a = expf((s_last[t] + tp[t * 8192]) - amax);
                A[t] = a + expf((s_last[t + 32] + tp[(t + 32) * 8192]) - amax);
            }
            float mm = logf(tree32(A)) + amax;
            float lsiv = (s_xl[p >> 6] + s_xs[p & 63]) + mm;
            g_LSL[(rbase + i) * 8192 + p] = lsiv;
        }

        // barrier across the 4 CTAs of this batch
        __threadfence();
        __syncthreads();
        if (tid == 0) {
            atomicAdd(&g_cnt[b], 1u);
            unsigned target = 4u * (unsigned)i;
            unsigned v;
            do { v = *(volatile unsigned*)&g_cnt[b]; } while (v < target);
        }
        __syncthreads();
        __threadfence();

        // reload full row i, compute carry (redundant per CTA, identical bits)
        for (int p = tid; p < 8192; p += 1024)
            s_lsi[p] = g_LSL[(rbase + i) * 8192 + p];
        __syncthreads();
        if (tid < S_DIM) {
            float amax = -INFINITY;
            for (int l = 0; l < L_DIM; ++l) amax = fmaxf(amax, s_lsi[l * 64 + tid]);
            float A[32];
            #pragma unroll 1
            for (int t = 0; t < 32; ++t) {
                float a = expf(s_lsi[t * 64 + tid] - amax);
                a = a + expf(s_lsi[(t + 32) * 64 + tid] - amax);
                a = a + expf(s_lsi[(t + 64) * 64 + tid] - amax);
                a = a + expf(s_lsi[(t + 96) * 64 + tid] - amax);
                A[t] = a;
            }
            s_last[tid] = logf(tree32(A)) + amax;
        }
        __syncthreads();
    }
}

// ------------------------------------------------------------- backward ----
// 32 CTAs (one per batch), 128 threads.
__global__ __launch_bounds__(128) void bwd_literal(const float* __restrict__ tr,
                                                   float* __restrict__ out) {
    __shared__ float s_lrow[8192];
    __shared__ float s_ft[S_DIM];
    __shared__ float s_v[S_DIM];
    __shared__ float s_sc[L_DIM];
    __shared__ int s_m;

    const int b = blockIdx.x, tid = threadIdx.x;
    const size_t rbase = (size_t)b * T_DIM;

    if (tid < S_DIM) s_ft[tid] = 0.0f;       // i = T-1: no ft (adding +0.0f is exact)
    __syncthreads();

    for (int i = T_DIM - 1; i >= 0; --i) {
        for (int p = tid; p < 8192; p += 128)
            s_lrow[p] = g_LSL[(rbase + i) * 8192 + p];
        __syncthreads();

        // score[l] = LSE_s( fl(lsl[l,s] + ft[s]) ): row reduction —
        // lane partial x[t] + x[t+32], then tree
        {
            const int l = tid;
            float amax = -INFINITY;
            for (int s = 0; s < S_DIM; ++s)
                amax = fmaxf(amax, s_lrow[l * 64 + s] + s_ft[s]);
            float A[32];
            #pragma unroll 1
            for (int t = 0; t < 32; ++t) {
                float a = expf((s_lrow[l * 64 + t] + s_ft[t]) - amax);
                A[t] = a + expf((s_lrow[l * 64 + t + 32] + s_ft[t + 32]) - amax);
            }
            s_sc[l] = logf(tree32(A)) + amax;
        }
        __syncthreads();

        if (tid == 0) {                       // first-index argmax (jnp.argmax)
            float best = s_sc[0]; int m = 0;
            for (int l = 1; l < L_DIM; ++l)
                if (s_sc[l] > best) { best = s_sc[l]; m = l; }
            s_m = m;
            out[b * T_DIM + i] = (float)m;
        }
        __syncthreads();

        if (i > 0) {
            const int m = s_m;
            if (tid < S_DIM) s_v[tid] = s_lrow[m * 64 + tid] + s_ft[tid];
            __syncthreads();
            // ft'[s'] column reduction over 8192 rows: only row m's 64 terms are
            // nonzero (exp underflows to exact +0.0f for the -10000-masked rows,
            // and the live block is 64-aligned), so partial[t] reduces to
            // term(s=t) + term(s=t+32), then the same tree.
            float nf = 0.f;
            if (tid < S_DIM) {
                const int sp = tid;
                const float* tb = tr + (size_t)sp * 8192 + ((m & 1) * 64) * 64 + (m >> 1);
                float amax = -INFINITY;
                for (int s = 0; s < S_DIM; ++s)
                    amax = fmaxf(amax, s_v[s] + tb[s * 64]);
                float A[32];
                #pragma unroll 1
                for (int t = 0; t < 32; ++t) {
                    float a = expf((s_v[t] + tb[t * 64]) - amax);
                    A[t] = a + expf((s_v[t + 32] + tb[(t + 32) * 64]) - amax);
                }
                nf = logf(tree32(A)) + amax;
            }
            __syncthreads();
            if (tid < S_DIM) s_ft[tid] = nf;
            __syncthreads();
        }
    }
}

// ---------------------------------------------------------------- launch ---
extern "C" void kernel_launch(void* const* d_in, const int* in_sizes, int n_in,
                              void* d_out, int out_size) {
    // Bind inputs by element count (distinct): xl 4194304, xs 2097152, tr 524288
    const float* xl = nullptr;
    const float* xs = nullptr;
    const float* tr = nullptr;
    for (int i = 0; i < n_in; ++i) {
        if (in_sizes[i] == B_DIM * T_DIM * L_DIM)      xl = (const float*)d_in[i];
        else if (in_sizes[i] == B_DIM * T_DIM * S_DIM) xs = (const float*)d_in[i];
        else if (in_sizes[i] == S_DIM * L_DIM * S_DIM) tr = (const float*)d_in[i];
    }

    zero_cnt_kernel<<<1, 32>>>();
    fwd_literal<<<B_DIM * 4, 1024>>>(xl, xs, tr);
    bwd_literal<<<B_DIM, 128>>>(tr, (float*)d_out);
}

// round 17
// speedup vs baseline: 2.7761x; 2.7761x over previous
#include <cuda_runtime.h>
#include <cstdint>
#include <math.h>

// ---------------------------------------------------------------------------
// HiddenWFACRF: B=32, T=1024, L=128, S=64
//
// LITERAL f32 replication of the jax reference (XLA:GPU bit behavior), same
// arithmetic as the R16 PASSING kernel (rel_err == 0), rescheduled for speed:
//   * exp/log = libdevice expf/logf
//   * column reductions (k-sum, l-sum, ft-sum): partial[t] = ascending sum of
//     rows {t, t+32, (t+64, t+96)}, then binary tree (16,8,4,2,1)
//   * row reduction (score LSE over S=64): partial[t] = x[t] + x[t+32], tree
//   * maxes are order-free (fmax assoc/comm on finite data)
// Scheduling changes only (bit-identical values):
//   - all partial/tree loops fully unrolled (registers, no local memory)
//   - fwd: CTA (b,g) owns s-range [8g,8g+8) x all l; carry computed locally
//     (warp-per-s, shfl tree == tree32); inter-CTA exchange = 8 floats via
//     parity-double-buffered g_lastbuf (volatile), spin barrier on g_cnt
//   - bwd: warp-per-label scores (lane pair + shfl tree == tree32),
//     warp-parallel first-index argmax, register-prefetched row double buffer,
//     bit-identical relayout g_trD for contiguous ft-update loads
// Output: float32 labels, [B,T] row-major.
// ---------------------------------------------------------------------------

#define L_DIM 128
#define S_DIM 64
#define T_DIM 1024
#define B_DIM 32
#define FULLM 0xffffffffu

__device__ __align__(16) float g_LSL[(size_t)B_DIM * T_DIM * 8192];  // 1 GiB
__device__ float    g_lastbuf[2][B_DIM][S_DIM];
__device__ unsigned g_cnt[B_DIM];
__device__ __align__(16) float g_trD[S_DIM * L_DIM * S_DIM];         // [sp][m][s]

// ----------------------------------------------------------------- prep ----
__global__ void zero_cnt_kernel() {
    if (threadIdx.x < B_DIM) g_cnt[threadIdx.x] = 0u;
}

// bit-identical relayout: g_trD[sp][m][s] = tr[sp*8192 + (m&1)*4096 + s*64 + (m>>1)]
__global__ void prep_trD_kernel(const float* __restrict__ tr) {
    int idx = blockIdx.x * blockDim.x + threadIdx.x;   // exactly 512K threads
    int s  = idx & 63;
    int m  = (idx >> 6) & 127;
    int sp = idx >> 13;
    g_trD[idx] = tr[(size_t)sp * 8192 + (m & 1) * 4096 + s * 64 + (m >> 1)];
}

// ------------------------------------------------------------- forward -----
// 256 CTAs = 32 batches x 8 s-groups; 512 threads; 2 points (l,s) per thread.
__global__ __launch_bounds__(512) void fwd_opt(const float* __restrict__ xl,
                                               const float* __restrict__ xs,
                                               const float* __restrict__ tr) {
    __shared__ float s_last[S_DIM];
    __shared__ float s_lsi[8][132];       // [s_local][l], padded: conflict-free
    __shared__ float s_xl[L_DIM];
    __shared__ float s_xs8[8];

    const int cta = blockIdx.x;
    const int b = cta >> 3, g = cta & 7;
    const int tid = threadIdx.x;
    const int w = tid >> 5, lane = tid & 31;
    const size_t rbase = (size_t)b * T_DIM;
    const int s0 = g * 8;

    // ---- row 0: base = fl(xl + xs)
    if (tid < L_DIM) s_xl[tid] = xl[rbase * L_DIM + tid];
    if (tid < 8)     s_xs8[tid] = xs[rbase * S_DIM + s0 + tid];
    __syncthreads();
    #pragma unroll
    for (int h = 0; h < 2; ++h) {
        int pi = tid + h * 512;
        int l = pi >> 3, sl = pi & 7;
        float v = s_xl[l] + s_xs8[sl];
        s_lsi[sl][l] = v;
        g_LSL[rbase * 8192 + l * 64 + s0 + sl] = v;
    }
    __syncthreads();
    // carry row 0: warp w<8 handles s_local=w; lane partial over l=t,t+32,t+64,t+96
    if (w < 8) {
        float x0 = s_lsi[w][lane],      x1 = s_lsi[w][lane + 32];
        float x2 = s_lsi[w][lane + 64], x3 = s_lsi[w][lane + 96];
        float mx = fmaxf(fmaxf(x0, x1), fmaxf(x2, x3));
        #pragma unroll
        for (int o = 16; o; o >>= 1) mx = fmaxf(mx, __shfl_down_sync(FULLM, mx, o));
        mx = __shfl_sync(FULLM, mx, 0);
        float a = expf(x0 - mx);
        a = a + expf(x1 - mx);
        a = a + expf(x2 - mx);
        a = a + expf(x3 - mx);
        #pragma unroll
        for (int o = 16; o; o >>= 1) a = a + __shfl_down_sync(FULLM, a, o);
        if (lane == 0) g_lastbuf[0][b][s0 + w] = logf(a) + mx;
    }
    __threadfence();
    __syncthreads();
    if (tid == 0) {
        atomicAdd(&g_cnt[b], 1u);
        while (*(volatile unsigned*)&g_cnt[b] < 8u) {}
    }
    __syncthreads();
    if (tid < S_DIM) s_last[tid] = *((volatile float*)&g_lastbuf[0][b][tid]);
    __syncthreads();

    // ---- steps 1..T-1
    for (int i = 1; i < T_DIM; ++i) {
        if (tid < L_DIM) s_xl[tid] = xl[(rbase + i) * L_DIM + tid];
        if (tid < 8)     s_xs8[tid] = xs[(rbase + i) * S_DIM + s0 + tid];
        __syncthreads();

        #pragma unroll
        for (int h = 0; h < 2; ++h) {
            int pi = tid + h * 512;
            int l = pi >> 3, sl = pi & 7;
            const float* tp = tr + l * 64 + s0 + sl;     // + k*8192
            float amax = -INFINITY;
            #pragma unroll
            for (int k = 0; k < S_DIM; ++k)
                amax = fmaxf(amax, s_last[k] + tp[k * 8192]);
            float A[32];
            #pragma unroll
            for (int t = 0; t < 32; ++t) {
                float a = expf((s_last[t] + tp[t * 8192]) - amax);
                A[t] = a + expf((s_last[t + 32] + tp[(t + 32) * 8192]) - amax);
            }
            #pragma unroll
            for (int hh = 16; hh >= 1; hh >>= 1)
                #pragma unroll
                for (int t = 0; t < hh; ++t) A[t] = A[t] + A[t + hh];
            float mm = logf(A[0]) + amax;
            float lsiv = (s_xl[l] + s_xs8[sl]) + mm;
            s_lsi[sl][l] = lsiv;
            g_LSL[(rbase + i) * 8192 + l * 64 + s0 + sl] = lsiv;
        }
        __syncthreads();

        if (i < T_DIM - 1) {
            // carry: warp-per-s, lane partials over l (strided-32, ascending chain)
            if (w < 8) {
                float x0 = s_lsi[w][lane],      x1 = s_lsi[w][lane + 32];
                float x2 = s_lsi[w][lane + 64], x3 = s_lsi[w][lane + 96];
                float mx = fmaxf(fmaxf(x0, x1), fmaxf(x2, x3));
                #pragma unroll
                for (int o = 16; o; o >>= 1) mx = fmaxf(mx, __shfl_down_sync(FULLM, mx, o));
                mx = __shfl_sync(FULLM, mx, 0);
                float a = expf(x0 - mx);
                a = a + expf(x1 - mx);
                a = a + expf(x2 - mx);
                a = a + expf(x3 - mx);
                #pragma unroll
                for (int o = 16; o; o >>= 1) a = a + __shfl_down_sync(FULLM, a, o);
                if (lane == 0) g_lastbuf[i & 1][b][s0 + w] = logf(a) + mx;
            }
            __threadfence();
            __syncthreads();
            if (tid == 0) {
                atomicAdd(&g_cnt[b], 1u);
                unsigned target = 8u * (unsigned)(i + 1);
                while (*(volatile unsigned*)&g_cnt[b] < target) {}
            }
            __syncthreads();
            if (tid < S_DIM) s_last[tid] = *((volatile float*)&g_lastbuf[i & 1][b][tid]);
            __syncthreads();
        }
    }
}

// ------------------------------------------------------------- backward ----
// 32 CTAs (one per batch), 256 threads (8 warps).
__global__ __launch_bounds__(256) void bwd_opt(float* __restrict__ out) {
    __shared__ float s_lrow[8192];        // 32 KB, current row
    __shared__ float s_ft[S_DIM], s_v[S_DIM], s_sc[L_DIM];
    __shared__ int s_m;

    const int b = blockIdx.x, tid = threadIdx.x;
    const int w = tid >> 5, lane = tid & 31;
    const size_t rbase = (size_t)b * T_DIM;

    if (tid < S_DIM) s_ft[tid] = 0.0f;    // i = T-1: no ft (+0.0f is exact)
    {   // load row T-1
        const float4* src = (const float4*)(g_LSL + (rbase + T_DIM - 1) * 8192);
        #pragma unroll
        for (int j = 0; j < 8; ++j) ((float4*)s_lrow)[tid + j * 256] = src[tid + j * 256];
    }
    __syncthreads();

    for (int i = T_DIM - 1; i >= 0; --i) {
        // prefetch row i-1 into registers (independent of smem)
        float4 nf[8];
        if (i > 0) {
            const float4* src = (const float4*)(g_LSL + (rbase + i - 1) * 8192);
            #pragma unroll
            for (int j = 0; j < 8; ++j) nf[j] = src[tid + j * 256];
        }

        // scores: warp w handles labels l = w, w+8, ..., w+120.
        // lane partial = exp(x[t]-mx) + exp(x[t+32]-mx), then shfl tree == tree32.
        #pragma unroll 1
        for (int li = 0; li < 16; ++li) {
            int l = w + li * 8;
            float v0 = s_lrow[l * 64 + lane]      + s_ft[lane];
            float v1 = s_lrow[l * 64 + lane + 32] + s_ft[lane + 32];
            float mx = fmaxf(v0, v1);
            #pragma unroll
            for (int o = 16; o; o >>= 1) mx = fmaxf(mx, __shfl_down_sync(FULLM, mx, o));
            mx = __shfl_sync(FULLM, mx, 0);
            float a = expf(v0 - mx) + expf(v1 - mx);
            #pragma unroll
            for (int o = 16; o; o >>= 1) a = a + __shfl_down_sync(FULLM, a, o);
            if (lane == 0) s_sc[l] = logf(a) + mx;
        }
        __syncthreads();

        // first-index argmax (strict >, ties -> lower index): warp 0
        if (w == 0) {
            float bv = s_sc[lane]; int bi = lane;
            #pragma unroll
            for (int j = 1; j < 4; ++j) {
                float v = s_sc[lane + 32 * j];
                if (v > bv) { bv = v; bi = lane + 32 * j; }
            }
            #pragma unroll
            for (int o = 16; o; o >>= 1) {
                float ov = __shfl_down_sync(FULLM, bv, o);
                int   oi = __shfl_down_sync(FULLM, bi, o);
                if (ov > bv || (ov == bv && oi < bi)) { bv = ov; bi = oi; }
            }
            if (lane == 0) { s_m = bi; out[b * T_DIM + i] = (float)bi; }
        }
        __syncthreads();

        if (i > 0) {
            const int m = s_m;
            if (tid < S_DIM) s_v[tid] = s_lrow[m * 64 + tid] + s_ft[tid];
            __syncthreads();
            // ft'[sp]: thread-per-sp, fully unrolled; contiguous loads from g_trD
            float nfval = 0.f;
            if (tid < S_DIM) {
                const float* td = g_trD + (size_t)tid * 8192 + m * 64;  // 64 contiguous
                float amax = -INFINITY;
                #pragma unroll
                for (int s = 0; s < S_DIM; ++s)
                    amax = fmaxf(amax, s_v[s] + td[s]);
                float A[32];
                #pragma unroll
                for (int t = 0; t < 32; ++t) {
                    float a = expf((s_v[t] + td[t]) - amax);
                    A[t] = a + expf((s_v[t + 32] + td[t + 32]) - amax);
                }
                #pragma unroll
                for (int hh = 16; hh >= 1; hh >>= 1)
                    #pragma unroll
                    for (int t = 0; t < hh; ++t) A[t] = A[t] + A[t + hh];
                nfval = logf(A[0]) + amax;
            }
            __syncthreads();
            if (tid < S_DIM) s_ft[tid] = nfval;
            // commit prefetched row (all reads of current row are done)
            #pragma unroll
            for (int j = 0; j < 8; ++j) ((float4*)s_lrow)[tid + j * 256] = nf[j];
            __syncthreads();
        }
    }
}

// ---------------------------------------------------------------- launch ---
extern "C" void kernel_launch(void* const* d_in, const int* in_sizes, int n_in,
                              void* d_out, int out_size) {
    // Bind inputs by element count (distinct): xl 4194304, xs 2097152, tr 524288
    const float* xl = nullptr;
    const float* xs = nullptr;
    const float* tr = nullptr;
    for (int i = 0; i < n_in; ++i) {
        if (in_sizes[i] == B_DIM * T_DIM * L_DIM)      xl = (const float*)d_in[i];
        else if (in_sizes[i] == B_DIM * T_DIM * S_DIM) xs = (const float*)d_in[i];
        else if (in_sizes[i] == S_DIM * L_DIM * S_DIM) tr = (const float*)d_in[i];
    }

    zero_cnt_kernel<<<1, 32>>>();
    prep_trD_kernel<<<S_DIM * L_DIM * S_DIM / 256, 256>>>(tr);
    fwd_opt<<<B_DIM * 8, 512>>>(xl, xs, tr);
    bwd_opt<<<B_DIM, 256>>>((float*)d_out);
}